// round 10
// baseline (speedup 1.0000x reference)
#include <cuda_runtime.h>

#define NT 128
#define NH 8
#define NL 3
#define LOG2E 1.4426950408889634f

#define O_WK  0
#define O_WQ  24
#define O_WV  48
#define O_WP  72
#define O_BP  96
#define O_W1  99
#define O_B1  111
#define O_W2  123
#define O_B2  135
#define O_WLM 138
#define O_BLM 139
#define NWTS  140

__device__ __forceinline__ float ex2(float x) {
    float y;
    asm("ex2.approx.ftz.f32 %0, %1;" : "=f"(y) : "f"(x));
    return y;
}

// warp max/min of NON-NEGATIVE floats via integer redux (bit pattern monotonic)
__device__ __forceinline__ float redux_max_nn(float x) {
    unsigned r;
    asm("redux.sync.max.u32 %0, %1, 0xffffffff;" : "=r"(r) : "r"(__float_as_uint(x)));
    return __uint_as_float(r);
}
__device__ __forceinline__ float redux_min_nn(float x) {
    unsigned r;
    asm("redux.sync.min.u32 %0, %1, 0xffffffff;" : "=r"(r) : "r"(__float_as_uint(x)));
    return __uint_as_float(r);
}

struct OS { float m, d, n; };
__device__ __forceinline__ OS comb(OS a, OS b) {
    float mx = fmaxf(a.m, b.m);
    float mn = fminf(a.m, b.m);
    float e  = ex2(mn - mx);
    bool  bl = a.m < b.m;
    float sa = bl ? e : 1.0f;
    float sb = bl ? 1.0f : e;
    OS r; r.m = mx; r.d = fmaf(a.d, sa, b.d * sb); r.n = fmaf(a.n, sa, b.n * sb);
    return r;
}

__global__ __launch_bounds__(256) void cat_kernel(
    const float* __restrict__ X,
    const float* __restrict__ wk, const float* __restrict__ wq, const float* __restrict__ wv,
    const float* __restrict__ Wp, const float* __restrict__ bp,
    const float* __restrict__ W1, const float* __restrict__ b1,
    const float* __restrict__ W2, const float* __restrict__ b2,
    const float* __restrict__ w_lm, const float* __restrict__ b_lm,
    float* __restrict__ out)
{
    __shared__ float  W[NWTS];
    __shared__ float4 py[2][NH][32];   // [buffer][warp=head][lane]

    const int tid   = threadIdx.x;
    const int wr    = tid >> 5;        // 0..7: head id
    const int lid   = tid & 31;
    const int batch = blockIdx.x;

    if (tid < NWTS) {
        int i = tid;
        float v;
        if      (i < 24)  v = wk[i];
        else if (i < 48)  v = wq[i - 24];
        else if (i < 72)  v = wv[i - 48];
        else if (i < 96)  v = Wp[i - 72];
        else if (i < 99)  v = bp[i - 96];
        else if (i < 111) v = W1[i - 99];
        else if (i < 123) v = b1[i - 111];
        else if (i < 135) v = W2[i - 123];
        else if (i < 138) v = b2[i - 135];
        else if (i == 138) v = w_lm[0];
        else               v = b_lm[0];
        W[i] = v;
    }

    float4 xv = reinterpret_cast<const float4*>(X + batch * NT)[lid];
    float x0 = xv.x, x1 = xv.y, x2 = xv.z, x3 = xv.w;
    __syncthreads();

    // hoist this head's per-layer weights into registers
    float c_r[NL], coef_r[NL], ca_r[NL];
    #pragma unroll
    for (int l = 0; l < NL; ++l) {
        float cc = W[O_WK + l*NH + wr] * W[O_WQ + l*NH + wr] * LOG2E;
        c_r[l]    = cc;
        ca_r[l]   = fabsf(cc);
        coef_r[l] = W[O_WV + l*NH + wr] * W[O_WP + l*NH + wr];
    }

    #pragma unroll
    for (int l = 0; l < NL; ++l) {
        const float u0 = x0*x0, u1 = x1*x1, u2 = x2*x2, u3 = x3*x3;

        const float umx = redux_max_nn(fmaxf(fmaxf(u0, u1), fmaxf(u2, u3)));
        const float umn = redux_min_nn(fminf(fminf(u0, u1), fminf(u2, u3)));

        const float ch = c_r[l];
        const float cf = coef_r[l];

        float py0, py1, py2, py3;

        if (ca_r[l] * (umx - umn) < 120.0f) {
            // ---- single-window additive scan (terms >= 2^-57, no FTZ) ----
            const float K = ((ch > 0.0f) ? ch * umx : ch * umn) - 63.0f;
            float e0 = ex2(fmaf(ch, u0, -K));
            float e1 = ex2(fmaf(ch, u1, -K));
            float e2 = ex2(fmaf(ch, u2, -K));
            float e3 = ex2(fmaf(ch, u3, -K));
            float n0 = e0*x0, n1 = e1*x1, n2 = e2*x2, n3 = e3*x3;

            float d01 = e0 + e1, m01 = n0 + n1;
            float d012 = d01 + e2, m012 = m01 + n2;
            float dT = d012 + e3, mT = m012 + n3;

            float sd = dT, sn = mT;
            #pragma unroll
            for (int o = 1; o < 32; o <<= 1) {
                float ud = __shfl_up_sync(0xffffffffu, sd, o);
                float un = __shfl_up_sync(0xffffffffu, sn, o);
                if (lid >= o) { sd += ud; sn += un; }
            }
            // exclusive prefix entering this lane = inclusive - local total
            float Pd = sd - dT;
            float Pn = sn - mT;

            float h0 = (lid == 0) ? 0.0f : __fdividef(Pn, Pd);
            float h1 = __fdividef(Pn + n0,   Pd + e0);
            float h2 = __fdividef(Pn + m01,  Pd + d01);
            float h3 = __fdividef(Pn + m012, Pd + d012);
            py0 = h0 * cf; py1 = h1 * cf; py2 = h2 * cf; py3 = h3 * cf;
        } else {
            // ---- exact monoid fallback ----
            OS a0 = { ch*u0, 1.0f, x0 };
            OS a1 = comb(a0, { ch*u1, 1.0f, x1 });
            OS a2 = comb(a1, { ch*u2, 1.0f, x2 });
            OS a3 = comb(a2, { ch*u3, 1.0f, x3 });
            OS agg = a3;
            #pragma unroll
            for (int o = 1; o < 32; o <<= 1) {
                OS up;
                up.m = __shfl_up_sync(0xffffffffu, agg.m, o);
                up.d = __shfl_up_sync(0xffffffffu, agg.d, o);
                up.n = __shfl_up_sync(0xffffffffu, agg.n, o);
                if (lid >= o) agg = comb(up, agg);
            }
            OS P;
            P.m = __shfl_up_sync(0xffffffffu, agg.m, 1);
            P.d = __shfl_up_sync(0xffffffffu, agg.d, 1);
            P.n = __shfl_up_sync(0xffffffffu, agg.n, 1);
            if (lid == 0) { P.m = -1e30f; P.d = 0.0f; P.n = 0.0f; }
            OS q1 = comb(P, a0);
            OS q2 = comb(P, a1);
            OS q3 = comb(P, a2);
            float h0 = (lid == 0) ? 0.0f : __fdividef(P.n, P.d);
            py0 = h0 * cf;
            py1 = __fdividef(q1.n, q1.d) * cf;
            py2 = __fdividef(q2.n, q2.d) * cf;
            py3 = __fdividef(q3.n, q3.d) * cf;
        }

        // ---- exchange partial y among 8 warps (1 barrier, dbl-buffered) ----
        const int buf = l & 1;
        py[buf][wr][lid] = make_float4(py0, py1, py2, py3);
        __syncthreads();
        const float bpv = W[O_BP + l];
        float y0 = bpv, y1 = bpv, y2 = bpv, y3 = bpv;
        #pragma unroll
        for (int w = 0; w < NH; ++w) {
            float4 p = py[buf][w][lid];
            y0 += p.x; y1 += p.y; y2 += p.z; y3 += p.w;
        }

        // ---- FF (redundant in all warps, register-local) ----
        const float b2v = W[O_B2 + l];
        const float w10 = W[O_W1 + l*4 + 0], w11 = W[O_W1 + l*4 + 1], w12 = W[O_W1 + l*4 + 2], w13 = W[O_W1 + l*4 + 3];
        const float b10 = W[O_B1 + l*4 + 0], b11 = W[O_B1 + l*4 + 1], b12 = W[O_B1 + l*4 + 2], b13 = W[O_B1 + l*4 + 3];
        const float w20 = W[O_W2 + l*4 + 0], w21 = W[O_W2 + l*4 + 1], w22 = W[O_W2 + l*4 + 2], w23 = W[O_W2 + l*4 + 3];
        #define FF(y_) ({                                                     \
            float f_ = b2v;                                                   \
            f_ = fmaf(fmaxf(fmaf((y_), w10, b10), 0.0f), w20, f_);            \
            f_ = fmaf(fmaxf(fmaf((y_), w11, b11), 0.0f), w21, f_);            \
            f_ = fmaf(fmaxf(fmaf((y_), w12, b12), 0.0f), w22, f_);            \
            f_ = fmaf(fmaxf(fmaf((y_), w13, b13), 0.0f), w23, f_);            \
            (y_) + f_; })
        x0 = FF(y0); x1 = FF(y1); x2 = FF(y2); x3 = FF(y3);
        #undef FF
    }

    if (wr == 0) {
        const float wl = W[O_WLM], bl = W[O_BLM];
        float4 ov;
        ov.x = fmaf(x0, wl, bl);
        ov.y = fmaf(x1, wl, bl);
        ov.z = fmaf(x2, wl, bl);
        ov.w = fmaf(x3, wl, bl);
        reinterpret_cast<float4*>(out + batch * NT)[lid] = ov;
    }
}

extern "C" void kernel_launch(void* const* d_in, const int* in_sizes, int n_in,
                              void* d_out, int out_size) {
    (void)in_sizes; (void)n_in; (void)out_size;
    cat_kernel<<<512, 256>>>(
        (const float*)d_in[0],  // X
        (const float*)d_in[1],  // wk
        (const float*)d_in[2],  // wq
        (const float*)d_in[3],  // wv
        (const float*)d_in[4],  // Wp
        (const float*)d_in[5],  // bp
        (const float*)d_in[6],  // W1
        (const float*)d_in[7],  // b1
        (const float*)d_in[8],  // W2
        (const float*)d_in[9],  // b2
        (const float*)d_in[10], // w_lm
        (const float*)d_in[11], // b_lm
        (float*)d_out);
}

// round 11
// speedup vs baseline: 1.0464x; 1.0464x over previous
#include <cuda_runtime.h>

#define NT 128
#define NH 8
#define NL 3
#define LOG2E 1.4426950408889634f

#define O_WK  0
#define O_WQ  24
#define O_WV  48
#define O_WP  72
#define O_BP  96
#define O_W1  99
#define O_B1  111
#define O_W2  123
#define O_B2  135
#define O_WLM 138
#define O_BLM 139
#define NWTS  140

__device__ __forceinline__ float ex2(float x) {
    float y;
    asm("ex2.approx.ftz.f32 %0, %1;" : "=f"(y) : "f"(x));
    return y;
}

// warp max/min of NON-NEGATIVE floats via integer redux (bit pattern monotonic)
__device__ __forceinline__ float redux_max_nn(float x) {
    unsigned r;
    asm("redux.sync.max.u32 %0, %1, 0xffffffff;" : "=r"(r) : "r"(__float_as_uint(x)));
    return __uint_as_float(r);
}
__device__ __forceinline__ float redux_min_nn(float x) {
    unsigned r;
    asm("redux.sync.min.u32 %0, %1, 0xffffffff;" : "=r"(r) : "r"(__float_as_uint(x)));
    return __uint_as_float(r);
}

struct OS { float m, d, n; };
__device__ __forceinline__ OS comb(OS a, OS b) {
    float mx = fmaxf(a.m, b.m);
    float mn = fminf(a.m, b.m);
    float e  = ex2(mn - mx);
    bool  bl = a.m < b.m;
    float sa = bl ? e : 1.0f;
    float sb = bl ? 1.0f : e;
    OS r; r.m = mx; r.d = fmaf(a.d, sa, b.d * sb); r.n = fmaf(a.n, sa, b.n * sb);
    return r;
}

__global__ __launch_bounds__(128) void cat_kernel(
    const float* __restrict__ X,
    const float* __restrict__ wk, const float* __restrict__ wq, const float* __restrict__ wv,
    const float* __restrict__ Wp, const float* __restrict__ bp,
    const float* __restrict__ W1, const float* __restrict__ b1,
    const float* __restrict__ W2, const float* __restrict__ b2,
    const float* __restrict__ w_lm, const float* __restrict__ b_lm,
    float* __restrict__ out)
{
    __shared__ float  W[NWTS];
    __shared__ float4 py[2][4][32];   // [buffer][warp][lane]

    const int tid   = threadIdx.x;
    const int wr    = tid >> 5;       // 0..3: which pair of heads
    const int lid   = tid & 31;
    const int batch = blockIdx.x;

    // start the X load early so its latency overlaps the weight staging
    float4 xv = reinterpret_cast<const float4*>(X + batch * NT)[lid];

    for (int i = tid; i < NWTS; i += 128) {
        float v;
        if      (i < 24)  v = wk[i];
        else if (i < 48)  v = wq[i - 24];
        else if (i < 72)  v = wv[i - 48];
        else if (i < 96)  v = Wp[i - 72];
        else if (i < 99)  v = bp[i - 96];
        else if (i < 111) v = W1[i - 99];
        else if (i < 123) v = b1[i - 111];
        else if (i < 135) v = W2[i - 123];
        else if (i < 138) v = b2[i - 135];
        else if (i == 138) v = w_lm[0];
        else               v = b_lm[0];
        W[i] = v;
    }
    __syncthreads();

    // ---- hoist EVERYTHING this warp touches into registers (loop fully unrolled,
    //      so these arrays become registers; per-layer smem reads vanish) ----
    float c_r[NL][2], coef_r[NL][2], camax_r[NL];
    float bp_r[NL], b2_r[NL];
    float w1_r[NL][4], b1_r[NL][4], w2_r[NL][4];
    #pragma unroll
    for (int l = 0; l < NL; ++l) {
        #pragma unroll
        for (int hh = 0; hh < 2; ++hh) {
            const int hg = wr * 2 + hh;
            float cc = W[O_WK + l*NH + hg] * W[O_WQ + l*NH + hg] * LOG2E;
            c_r[l][hh]    = cc;
            coef_r[l][hh] = W[O_WV + l*NH + hg] * W[O_WP + l*NH + hg];
        }
        camax_r[l] = fmaxf(fabsf(c_r[l][0]), fabsf(c_r[l][1]));
        bp_r[l] = W[O_BP + l];
        b2_r[l] = W[O_B2 + l];
        #pragma unroll
        for (int k = 0; k < 4; ++k) {
            w1_r[l][k] = W[O_W1 + l*4 + k];
            b1_r[l][k] = W[O_B1 + l*4 + k];
            w2_r[l][k] = W[O_W2 + l*4 + k];
        }
    }
    const float wlm = W[O_WLM], blm = W[O_BLM];

    float x0 = xv.x, x1 = xv.y, x2 = xv.z, x3 = xv.w;

    #pragma unroll
    for (int l = 0; l < NL; ++l) {
        const float u0 = x0*x0, u1 = x1*x1, u2 = x2*x2, u3 = x3*x3;

        const float umx = redux_max_nn(fmaxf(fmaxf(u0, u1), fmaxf(u2, u3)));
        const float umn = redux_min_nn(fminf(fminf(u0, u1), fminf(u2, u3)));

        const float c0 = c_r[l][0], c1 = c_r[l][1];
        const float cf0 = coef_r[l][0], cf1 = coef_r[l][1];

        float py0 = 0.f, py1 = 0.f, py2 = 0.f, py3 = 0.f;

        if (camax_r[l] * (umx - umn) < 120.0f) {
            // ---- 2 heads, single-window additive scans, stages interleaved ----
            float e0a[2], n0a[2], d01[2], m01[2], d012[2], m012[2];
            float dT[2], mT[2], sd[2], sn[2];
            const float cc[2] = { c0, c1 };
            #pragma unroll
            for (int hh = 0; hh < 2; ++hh) {
                const float ch = cc[hh];
                const float K  = ((ch > 0.0f) ? ch * umx : ch * umn) - 63.0f;
                float e0 = ex2(fmaf(ch, u0, -K));
                float e1 = ex2(fmaf(ch, u1, -K));
                float e2 = ex2(fmaf(ch, u2, -K));
                float e3 = ex2(fmaf(ch, u3, -K));
                float n0 = e0*x0, n1 = e1*x1, n2 = e2*x2, n3 = e3*x3;
                float a  = e0 + e1;  float b_  = n0 + n1;
                float a2 = a + e2;   float b2_ = b_ + n2;
                e0a[hh] = e0;  n0a[hh] = n0;
                d01[hh] = a;   m01[hh] = b_;
                d012[hh] = a2; m012[hh] = b2_;
                dT[hh] = a2 + e3; mT[hh] = b2_ + n3;
                sd[hh] = dT[hh];  sn[hh] = mT[hh];
            }
            #pragma unroll
            for (int o = 1; o < 32; o <<= 1) {
                float ud0 = __shfl_up_sync(0xffffffffu, sd[0], o);
                float un0 = __shfl_up_sync(0xffffffffu, sn[0], o);
                float ud1 = __shfl_up_sync(0xffffffffu, sd[1], o);
                float un1 = __shfl_up_sync(0xffffffffu, sn[1], o);
                if (lid >= o) {
                    sd[0] += ud0; sn[0] += un0;
                    sd[1] += ud1; sn[1] += un1;
                }
            }
            const float cf[2] = { cf0, cf1 };
            #pragma unroll
            for (int hh = 0; hh < 2; ++hh) {
                float Pd = sd[hh] - dT[hh];
                float Pn = sn[hh] - mT[hh];
                float h0 = (lid == 0) ? 0.0f : __fdividef(Pn, Pd);
                float h1 = __fdividef(Pn + n0a[hh],  Pd + e0a[hh]);
                float h2 = __fdividef(Pn + m01[hh],  Pd + d01[hh]);
                float h3 = __fdividef(Pn + m012[hh], Pd + d012[hh]);
                py0 = fmaf(h0, cf[hh], py0);
                py1 = fmaf(h1, cf[hh], py1);
                py2 = fmaf(h2, cf[hh], py2);
                py3 = fmaf(h3, cf[hh], py3);
            }
        } else {
            // ---- exact monoid fallback for both heads ----
            const float cc[2] = { c0, c1 };
            const float cf[2] = { cf0, cf1 };
            #pragma unroll
            for (int hh = 0; hh < 2; ++hh) {
                const float ch = cc[hh];
                OS a0 = { ch*u0, 1.0f, x0 };
                OS a1 = comb(a0, { ch*u1, 1.0f, x1 });
                OS a2 = comb(a1, { ch*u2, 1.0f, x2 });
                OS a3 = comb(a2, { ch*u3, 1.0f, x3 });
                OS agg = a3;
                #pragma unroll
                for (int o = 1; o < 32; o <<= 1) {
                    OS up;
                    up.m = __shfl_up_sync(0xffffffffu, agg.m, o);
                    up.d = __shfl_up_sync(0xffffffffu, agg.d, o);
                    up.n = __shfl_up_sync(0xffffffffu, agg.n, o);
                    if (lid >= o) agg = comb(up, agg);
                }
                OS P;
                P.m = __shfl_up_sync(0xffffffffu, agg.m, 1);
                P.d = __shfl_up_sync(0xffffffffu, agg.d, 1);
                P.n = __shfl_up_sync(0xffffffffu, agg.n, 1);
                if (lid == 0) { P.m = -1e30f; P.d = 0.0f; P.n = 0.0f; }
                OS q1 = comb(P, a0);
                OS q2 = comb(P, a1);
                OS q3 = comb(P, a2);
                float h0 = (lid == 0) ? 0.0f : __fdividef(P.n, P.d);
                py0 = fmaf(h0, cf[hh], py0);
                py1 = fmaf(__fdividef(q1.n, q1.d), cf[hh], py1);
                py2 = fmaf(__fdividef(q2.n, q2.d), cf[hh], py2);
                py3 = fmaf(__fdividef(q3.n, q3.d), cf[hh], py3);
            }
        }

        // ---- exchange partial y among 4 warps (1 barrier, dbl-buffered) ----
        const int buf = l & 1;
        py[buf][wr][lid] = make_float4(py0, py1, py2, py3);
        __syncthreads();
        const float bpv = bp_r[l];
        float4 pa = py[buf][0][lid];
        float4 pb = py[buf][1][lid];
        float4 pc = py[buf][2][lid];
        float4 pd = py[buf][3][lid];
        float y0 = (pa.x + pb.x) + (pc.x + pd.x) + bpv;
        float y1 = (pa.y + pb.y) + (pc.y + pd.y) + bpv;
        float y2 = (pa.z + pb.z) + (pc.z + pd.z) + bpv;
        float y3 = (pa.w + pb.w) + (pc.w + pd.w) + bpv;

        // ---- FF (redundant in all warps, fully register-resident) ----
        const float b2v = b2_r[l];
        const float w10 = w1_r[l][0], w11 = w1_r[l][1], w12 = w1_r[l][2], w13 = w1_r[l][3];
        const float b10 = b1_r[l][0], b11 = b1_r[l][1], b12 = b1_r[l][2], b13 = b1_r[l][3];
        const float w20 = w2_r[l][0], w21 = w2_r[l][1], w22 = w2_r[l][2], w23 = w2_r[l][3];
        #define FF(y_) ({                                                     \
            float f_ = b2v;                                                   \
            f_ = fmaf(fmaxf(fmaf((y_), w10, b10), 0.0f), w20, f_);            \
            f_ = fmaf(fmaxf(fmaf((y_), w11, b11), 0.0f), w21, f_);            \
            f_ = fmaf(fmaxf(fmaf((y_), w12, b12), 0.0f), w22, f_);            \
            f_ = fmaf(fmaxf(fmaf((y_), w13, b13), 0.0f), w23, f_);            \
            (y_) + f_; })
        x0 = FF(y0); x1 = FF(y1); x2 = FF(y2); x3 = FF(y3);
        #undef FF
    }

    if (wr == 0) {
        float4 ov;
        ov.x = fmaf(x0, wlm, blm);
        ov.y = fmaf(x1, wlm, blm);
        ov.z = fmaf(x2, wlm, blm);
        ov.w = fmaf(x3, wlm, blm);
        reinterpret_cast<float4*>(out + batch * NT)[lid] = ov;
    }
}

extern "C" void kernel_launch(void* const* d_in, const int* in_sizes, int n_in,
                              void* d_out, int out_size) {
    (void)in_sizes; (void)n_in; (void)out_size;
    cat_kernel<<<512, 128>>>(
        (const float*)d_in[0],  // X
        (const float*)d_in[1],  // wk
        (const float*)d_in[2],  // wq
        (const float*)d_in[3],  // wv
        (const float*)d_in[4],  // Wp
        (const float*)d_in[5],  // bp
        (const float*)d_in[6],  // W1
        (const float*)d_in[7],  // b1
        (const float*)d_in[8],  // W2
        (const float*)d_in[9],  // b2
        (const float*)d_in[10], // w_lm
        (const float*)d_in[11], // b_lm
        (float*)d_out);
}

// round 12
// speedup vs baseline: 1.1401x; 1.0895x over previous
#include <cuda_runtime.h>

#define NT 128
#define NH 8
#define NL 3
#define LOG2E 1.4426950408889634f

#define O_WK  0
#define O_WQ  24
#define O_WV  48
#define O_WP  72
#define O_BP  96
#define O_W1  99
#define O_B1  111
#define O_W2  123
#define O_B2  135
#define O_WLM 138
#define O_BLM 139
#define NWTS  140

__device__ __forceinline__ float ex2(float x) {
    float y;
    asm("ex2.approx.ftz.f32 %0, %1;" : "=f"(y) : "f"(x));
    return y;
}

// warp max/min of NON-NEGATIVE floats via integer redux (bit pattern monotonic)
__device__ __forceinline__ float redux_max_nn(float x) {
    unsigned r;
    asm("redux.sync.max.u32 %0, %1, 0xffffffff;" : "=r"(r) : "r"(__float_as_uint(x)));
    return __uint_as_float(r);
}
__device__ __forceinline__ float redux_min_nn(float x) {
    unsigned r;
    asm("redux.sync.min.u32 %0, %1, 0xffffffff;" : "=r"(r) : "r"(__float_as_uint(x)));
    return __uint_as_float(r);
}

struct OS { float m, d, n; };
__device__ __forceinline__ OS comb(OS a, OS b) {
    float mx = fmaxf(a.m, b.m);
    float mn = fminf(a.m, b.m);
    float e  = ex2(mn - mx);
    bool  bl = a.m < b.m;
    float sa = bl ? e : 1.0f;
    float sb = bl ? 1.0f : e;
    OS r; r.m = mx; r.d = fmaf(a.d, sa, b.d * sb); r.n = fmaf(a.n, sa, b.n * sb);
    return r;
}

__global__ __launch_bounds__(128) void cat_kernel(
    const float* __restrict__ X,
    const float* __restrict__ wk, const float* __restrict__ wq, const float* __restrict__ wv,
    const float* __restrict__ Wp, const float* __restrict__ bp,
    const float* __restrict__ W1, const float* __restrict__ b1,
    const float* __restrict__ W2, const float* __restrict__ b2,
    const float* __restrict__ w_lm, const float* __restrict__ b_lm,
    float* __restrict__ out)
{
    __shared__ float  W[NWTS];
    __shared__ float  ps[4][NT];   // per-warp partial y, position-indexed
    __shared__ float  xs[NT];      // x broadcast between layers

    const int tid   = threadIdx.x;
    const int wr    = tid >> 5;    // 0..3: head pair; also position-phase for FF
    const int lid   = tid & 31;
    const int batch = blockIdx.x;

    // start the X load early so its latency overlaps the weight staging
    float4 xv = reinterpret_cast<const float4*>(X + batch * NT)[lid];

    for (int i = tid; i < NWTS; i += 128) {
        float v;
        if      (i < 24)  v = wk[i];
        else if (i < 48)  v = wq[i - 24];
        else if (i < 72)  v = wv[i - 48];
        else if (i < 96)  v = Wp[i - 72];
        else if (i < 99)  v = bp[i - 96];
        else if (i < 111) v = W1[i - 99];
        else if (i < 123) v = b1[i - 111];
        else if (i < 135) v = W2[i - 123];
        else if (i < 138) v = b2[i - 135];
        else if (i == 138) v = w_lm[0];
        else               v = b_lm[0];
        W[i] = v;
    }
    __syncthreads();

    // ---- hoist all per-warp weights into registers (arrays -> regs after unroll) ----
    float c_r[NL][2], coef_r[NL][2], camax_r[NL];
    float bp_r[NL], b2_r[NL];
    float w1_r[NL][4], b1_r[NL][4], w2_r[NL][4];
    #pragma unroll
    for (int l = 0; l < NL; ++l) {
        #pragma unroll
        for (int hh = 0; hh < 2; ++hh) {
            const int hg = wr * 2 + hh;
            float cc = W[O_WK + l*NH + hg] * W[O_WQ + l*NH + hg] * LOG2E;
            c_r[l][hh]    = cc;
            coef_r[l][hh] = W[O_WV + l*NH + hg] * W[O_WP + l*NH + hg];
        }
        camax_r[l] = fmaxf(fabsf(c_r[l][0]), fabsf(c_r[l][1]));
        bp_r[l] = W[O_BP + l];
        b2_r[l] = W[O_B2 + l];
        #pragma unroll
        for (int k = 0; k < 4; ++k) {
            w1_r[l][k] = W[O_W1 + l*4 + k];
            b1_r[l][k] = W[O_B1 + l*4 + k];
            w2_r[l][k] = W[O_W2 + l*4 + k];
        }
    }
    const float wlm = W[O_WLM], blm = W[O_BLM];

    float x0 = xv.x, x1 = xv.y, x2 = xv.z, x3 = xv.w;

    #pragma unroll
    for (int l = 0; l < NL; ++l) {
        const float u0 = x0*x0, u1 = x1*x1, u2 = x2*x2, u3 = x3*x3;

        const float umx = redux_max_nn(fmaxf(fmaxf(u0, u1), fmaxf(u2, u3)));
        const float umn = redux_min_nn(fminf(fminf(u0, u1), fminf(u2, u3)));

        const float c0 = c_r[l][0], c1 = c_r[l][1];
        const float cf0 = coef_r[l][0], cf1 = coef_r[l][1];

        float py0 = 0.f, py1 = 0.f, py2 = 0.f, py3 = 0.f;

        if (camax_r[l] * (umx - umn) < 120.0f) {
            // ---- 2 heads, single-window additive scans, stages interleaved ----
            float e0a[2], n0a[2], d01[2], m01[2], d012[2], m012[2];
            float dT[2], mT[2], sd[2], sn[2];
            const float cc[2] = { c0, c1 };
            #pragma unroll
            for (int hh = 0; hh < 2; ++hh) {
                const float ch = cc[hh];
                const float K  = ((ch > 0.0f) ? ch * umx : ch * umn) - 63.0f;
                float e0 = ex2(fmaf(ch, u0, -K));
                float e1 = ex2(fmaf(ch, u1, -K));
                float e2 = ex2(fmaf(ch, u2, -K));
                float e3 = ex2(fmaf(ch, u3, -K));
                float n0 = e0*x0, n1 = e1*x1, n2 = e2*x2, n3 = e3*x3;
                float a  = e0 + e1;  float b_  = n0 + n1;
                float a2 = a + e2;   float b2_ = b_ + n2;
                e0a[hh] = e0;  n0a[hh] = n0;
                d01[hh] = a;   m01[hh] = b_;
                d012[hh] = a2; m012[hh] = b2_;
                dT[hh] = a2 + e3; mT[hh] = b2_ + n3;
                sd[hh] = dT[hh];  sn[hh] = mT[hh];
            }
            #pragma unroll
            for (int o = 1; o < 32; o <<= 1) {
                float ud0 = __shfl_up_sync(0xffffffffu, sd[0], o);
                float un0 = __shfl_up_sync(0xffffffffu, sn[0], o);
                float ud1 = __shfl_up_sync(0xffffffffu, sd[1], o);
                float un1 = __shfl_up_sync(0xffffffffu, sn[1], o);
                if (lid >= o) {
                    sd[0] += ud0; sn[0] += un0;
                    sd[1] += ud1; sn[1] += un1;
                }
            }
            const float cf[2] = { cf0, cf1 };
            #pragma unroll
            for (int hh = 0; hh < 2; ++hh) {
                float Pd = sd[hh] - dT[hh];
                float Pn = sn[hh] - mT[hh];
                // lane 0: Pn=Pd=0 -> 0/(1e-37)=0, no select needed; elsewhere Pd >= 2^-57 >> 1e-37
                float h0 = __fdividef(Pn, Pd + 1e-37f);
                float h1 = __fdividef(Pn + n0a[hh],  Pd + e0a[hh]);
                float h2 = __fdividef(Pn + m01[hh],  Pd + d01[hh]);
                float h3 = __fdividef(Pn + m012[hh], Pd + d012[hh]);
                py0 = fmaf(h0, cf[hh], py0);
                py1 = fmaf(h1, cf[hh], py1);
                py2 = fmaf(h2, cf[hh], py2);
                py3 = fmaf(h3, cf[hh], py3);
            }
        } else {
            // ---- exact monoid fallback for both heads ----
            const float cc[2] = { c0, c1 };
            const float cf[2] = { cf0, cf1 };
            #pragma unroll
            for (int hh = 0; hh < 2; ++hh) {
                const float ch = cc[hh];
                OS a0 = { ch*u0, 1.0f, x0 };
                OS a1 = comb(a0, { ch*u1, 1.0f, x1 });
                OS a2 = comb(a1, { ch*u2, 1.0f, x2 });
                OS a3 = comb(a2, { ch*u3, 1.0f, x3 });
                OS agg = a3;
                #pragma unroll
                for (int o = 1; o < 32; o <<= 1) {
                    OS up;
                    up.m = __shfl_up_sync(0xffffffffu, agg.m, o);
                    up.d = __shfl_up_sync(0xffffffffu, agg.d, o);
                    up.n = __shfl_up_sync(0xffffffffu, agg.n, o);
                    if (lid >= o) agg = comb(up, agg);
                }
                OS P;
                P.m = __shfl_up_sync(0xffffffffu, agg.m, 1);
                P.d = __shfl_up_sync(0xffffffffu, agg.d, 1);
                P.n = __shfl_up_sync(0xffffffffu, agg.n, 1);
                if (lid == 0) { P.m = -1e30f; P.d = 0.0f; P.n = 0.0f; }
                OS q1 = comb(P, a0);
                OS q2 = comb(P, a1);
                OS q3 = comb(P, a2);
                float h0 = (lid == 0) ? 0.0f : __fdividef(P.n, P.d);
                py0 = fmaf(h0, cf[hh], py0);
                py1 = fmaf(__fdividef(q1.n, q1.d), cf[hh], py1);
                py2 = fmaf(__fdividef(q2.n, q2.d), cf[hh], py2);
                py3 = fmaf(__fdividef(q3.n, q3.d), cf[hh], py3);
            }
        }

        // ---- position-split epilogue ----
        // store this warp's partial y (position-indexed row)
        reinterpret_cast<float4*>(ps[wr])[lid] = make_float4(py0, py1, py2, py3);
        __syncthreads();

        // this warp owns positions 4*lid + wr: sum 4 partials + bias
        const int myp = 4 * lid + wr;
        float y = bp_r[l] + ps[0][myp] + ps[1][myp] + ps[2][myp] + ps[3][myp];

        // FF for one position only
        float f = b2_r[l];
        #pragma unroll
        for (int k = 0; k < 4; ++k)
            f = fmaf(fmaxf(fmaf(y, w1_r[l][k], b1_r[l][k]), 0.0f), w2_r[l][k], f);
        xs[myp] = y + f;
        __syncthreads();

        // redistribute x: each lane re-reads its 4 positions
        float4 xn = reinterpret_cast<const float4*>(xs)[lid];
        x0 = xn.x; x1 = xn.y; x2 = xn.z; x3 = xn.w;
    }

    if (wr == 0) {
        float4 ov;
        ov.x = fmaf(x0, wlm, blm);
        ov.y = fmaf(x1, wlm, blm);
        ov.z = fmaf(x2, wlm, blm);
        ov.w = fmaf(x3, wlm, blm);
        reinterpret_cast<float4*>(out + batch * NT)[lid] = ov;
    }
}

extern "C" void kernel_launch(void* const* d_in, const int* in_sizes, int n_in,
                              void* d_out, int out_size) {
    (void)in_sizes; (void)n_in; (void)out_size;
    cat_kernel<<<512, 128>>>(
        (const float*)d_in[0],  // X
        (const float*)d_in[1],  // wk
        (const float*)d_in[2],  // wq
        (const float*)d_in[3],  // wv
        (const float*)d_in[4],  // Wp
        (const float*)d_in[5],  // bp
        (const float*)d_in[6],  // W1
        (const float*)d_in[7],  // b1
        (const float*)d_in[8],  // W2
        (const float*)d_in[9],  // b2
        (const float*)d_in[10], // w_lm
        (const float*)d_in[11], // b_lm
        (float*)d_out);
}